// round 6
// baseline (speedup 1.0000x reference)
#include <cuda_runtime.h>
#include <cuda_bf16.h>

// GCNConv (1 in/out feature, self-loops, symmetric norm) + sigmoid.
// out[d] = sigmoid( dinv[d]*( SUM_{e:dst=d} dinv[src]*x[src]*W + dinv[d]*x[d]*W ) + b )
//
// Bottleneck (measured): chip-wide LTS random-op cap ~170 ops/cyc.
// Op budget: 32M degree REDs + 32M gathers + 32M scatter REDs + ~12M
// streaming sectors  =>  ~355us floor. This version trims node-side passes.

#define MAXN 1048576

__device__ int   g_ideg[MAXN];   // in-degree (self-loop = +1 at use site)
__device__ float g_y[MAXN];      // x * W * rsqrt(deg)
__device__ float g_S[MAXN];      // sum of incoming y[src]

// ---------------------------------------------------------------------------
// Zero only the degree array (S is zeroed by k_node's streaming pass).
__global__ void k_zero(int n4) {
    int i = blockIdx.x * blockDim.x + threadIdx.x;
    if (i < n4)
        reinterpret_cast<int4*>(g_ideg)[i] = make_int4(0, 0, 0, 0);
}
__global__ void k_zero_tail(int n4, int n) {
    int i = n4 * 4 + blockIdx.x * blockDim.x + threadIdx.x;
    if (i < n) g_ideg[i] = 0;
}

// ---------------------------------------------------------------------------
// Degree: 8 edges per thread (2x int4 coalesced reads), 8 REDs (L2-resident).
__global__ void k_degree(const int* __restrict__ dst, int e8, int e) {
    int i = blockIdx.x * blockDim.x + threadIdx.x;
    if (i < e8) {
        const int4* p = reinterpret_cast<const int4*>(dst) + i * 2;
        int4 a = p[0];
        int4 b = p[1];
        atomicAdd(&g_ideg[a.x], 1);
        atomicAdd(&g_ideg[a.y], 1);
        atomicAdd(&g_ideg[a.z], 1);
        atomicAdd(&g_ideg[a.w], 1);
        atomicAdd(&g_ideg[b.x], 1);
        atomicAdd(&g_ideg[b.y], 1);
        atomicAdd(&g_ideg[b.z], 1);
        atomicAdd(&g_ideg[b.w], 1);
    }
    int t = e8 * 8 + i;
    if (i < (e - e8 * 8)) {
        atomicAdd(&g_ideg[dst[t]], 1);
    }
}

// ---------------------------------------------------------------------------
// Per-node: y = x*W*rsqrt(deg+1); also zero S for the scatter pass.
__global__ void k_node(const float* __restrict__ x,
                       const float* __restrict__ W, int n4) {
    int i = blockIdx.x * blockDim.x + threadIdx.x;
    if (i < n4) {
        float w  = __ldg(W);
        int4  dg = reinterpret_cast<const int4*>(g_ideg)[i];
        float4 xv = reinterpret_cast<const float4*>(x)[i];
        float4 yv;
        yv.x = xv.x * w * rsqrtf((float)(dg.x + 1));
        yv.y = xv.y * w * rsqrtf((float)(dg.y + 1));
        yv.z = xv.z * w * rsqrtf((float)(dg.z + 1));
        yv.w = xv.w * w * rsqrtf((float)(dg.w + 1));
        reinterpret_cast<float4*>(g_y)[i] = yv;
        reinterpret_cast<float4*>(g_S)[i] = make_float4(0.f, 0.f, 0.f, 0.f);
    }
}
__global__ void k_node_tail(const float* __restrict__ x,
                            const float* __restrict__ W, int n4, int n) {
    int i = n4 * 4 + blockIdx.x * blockDim.x + threadIdx.x;
    if (i < n) {
        g_y[i] = x[i] * __ldg(W) * rsqrtf((float)(g_ideg[i] + 1));
        g_S[i] = 0.0f;
    }
}

// ---------------------------------------------------------------------------
// Scatter: 8 edges/thread. All 8 gathers issued first (MLP=8), then 8 REDs.
__global__ void k_scatter(const int* __restrict__ src,
                          const int* __restrict__ dst, int e8, int e) {
    int i = blockIdx.x * blockDim.x + threadIdx.x;
    if (i < e8) {
        const int4* ps = reinterpret_cast<const int4*>(src) + i * 2;
        const int4* pd = reinterpret_cast<const int4*>(dst) + i * 2;
        int4 s0 = ps[0];
        int4 s1 = ps[1];
        int4 d0 = pd[0];
        int4 d1 = pd[1];
        float v0 = __ldg(&g_y[s0.x]);
        float v1 = __ldg(&g_y[s0.y]);
        float v2 = __ldg(&g_y[s0.z]);
        float v3 = __ldg(&g_y[s0.w]);
        float v4 = __ldg(&g_y[s1.x]);
        float v5 = __ldg(&g_y[s1.y]);
        float v6 = __ldg(&g_y[s1.z]);
        float v7 = __ldg(&g_y[s1.w]);
        atomicAdd(&g_S[d0.x], v0);
        atomicAdd(&g_S[d0.y], v1);
        atomicAdd(&g_S[d0.z], v2);
        atomicAdd(&g_S[d0.w], v3);
        atomicAdd(&g_S[d1.x], v4);
        atomicAdd(&g_S[d1.y], v5);
        atomicAdd(&g_S[d1.z], v6);
        atomicAdd(&g_S[d1.w], v7);
    }
    int t = e8 * 8 + i;
    if (i < (e - e8 * 8)) {
        atomicAdd(&g_S[dst[t]], __ldg(&g_y[src[t]]));
    }
}

// ---------------------------------------------------------------------------
// Finalize: out = sigmoid(rsqrt(deg+1)*(S + y) + b).  dinv recomputed from
// ideg (cheaper than loading a stored dinv array: removes a 4MB store+read).
__global__ void k_final(float* __restrict__ out,
                        const float* __restrict__ b, int n4) {
    int i = blockIdx.x * blockDim.x + threadIdx.x;
    if (i < n4) {
        float bb = __ldg(b);
        int4   dg = reinterpret_cast<const int4*>(g_ideg)[i];
        float4 sv = reinterpret_cast<const float4*>(g_S)[i];
        float4 yv = reinterpret_cast<const float4*>(g_y)[i];
        float4 o;
        float z0 = rsqrtf((float)(dg.x + 1)) * (sv.x + yv.x) + bb;
        float z1 = rsqrtf((float)(dg.y + 1)) * (sv.y + yv.y) + bb;
        float z2 = rsqrtf((float)(dg.z + 1)) * (sv.z + yv.z) + bb;
        float z3 = rsqrtf((float)(dg.w + 1)) * (sv.w + yv.w) + bb;
        o.x = 1.0f / (1.0f + __expf(-z0));
        o.y = 1.0f / (1.0f + __expf(-z1));
        o.z = 1.0f / (1.0f + __expf(-z2));
        o.w = 1.0f / (1.0f + __expf(-z3));
        reinterpret_cast<float4*>(out)[i] = o;
    }
}
__global__ void k_final_tail(float* __restrict__ out,
                             const float* __restrict__ b, int n4, int n) {
    int i = n4 * 4 + blockIdx.x * blockDim.x + threadIdx.x;
    if (i < n) {
        float z = rsqrtf((float)(g_ideg[i] + 1)) * (g_S[i] + g_y[i]) + __ldg(b);
        out[i] = 1.0f / (1.0f + __expf(-z));
    }
}

// ---------------------------------------------------------------------------
extern "C" void kernel_launch(void* const* d_in, const int* in_sizes, int n_in,
                              void* d_out, int out_size) {
    const float* x    = (const float*)d_in[0];
    const int*   eidx = (const int*)  d_in[1];
    const float* W    = (const float*)d_in[2];
    const float* b    = (const float*)d_in[3];
    float* out = (float*)d_out;

    int n = in_sizes[0];
    int e = in_sizes[1] / 2;
    const int* src = eidx;
    const int* dst = eidx + e;

    int n4 = n / 4;
    int e8 = e / 8;

    const int TPBN = 256;
    const int TPBE = 512;
    int gn4 = (n4 + TPBN - 1) / TPBN;
    int ge8 = (e8 + TPBE - 1) / TPBE;

    k_zero   <<<gn4, TPBN>>>(n4);
    if (n % 4) k_zero_tail<<<1, 256>>>(n4, n);
    k_degree <<<ge8, TPBE>>>(dst, e8, e);
    k_node   <<<gn4, TPBN>>>(x, W, n4);
    if (n % 4) k_node_tail<<<1, 256>>>(x, W, n4, n);
    k_scatter<<<ge8, TPBE>>>(src, dst, e8, e);
    k_final  <<<gn4, TPBN>>>(out, b, n4);
    if (n % 4) k_final_tail<<<1, 256>>>(out, b, n4, n);
}

// round 7
// speedup vs baseline: 1.0016x; 1.0016x over previous
#include <cuda_runtime.h>
#include <cuda_bf16.h>

// GCNConv (1 in/out feature, self-loops, symmetric norm) + sigmoid.
// out[d] = sigmoid( dinv[d]*( SUM_{e:dst=d} dinv[src]*x[src]*W + dinv[d]*x[d]*W ) + b )
//
// Measured constraints:
//   k_scatter: 72M LTS sector/RMW ops @ ~169/cyc chip cap   -> ~236us (at cap)
//   k_degree : 32M REDs @ 148/cyc SMSP-issue class floor    -> ~120us floor
// This round removes the k_zero pass entirely: __device__ globals are
// zero-initialized at module load, and k_final restores ideg=0 / S=0 after
// consuming them, so the "arrays are zero at entry" invariant holds across
// graph replays. Deterministic: same work, same output, every call.

#define MAXN 1048576

__device__ int   g_ideg[MAXN];   // in-degree (self-loop = +1 at use site); 0 at entry
__device__ float g_y[MAXN];      // x * W * rsqrt(deg)
__device__ float g_S[MAXN];      // edge-sum accumulator; 0 at entry

// ---------------------------------------------------------------------------
// Degree: 16 edges per thread (4x int4 front-batched loads), 16 REDs.
__global__ void k_degree(const int* __restrict__ dst, int e16, int e) {
    int i = blockIdx.x * blockDim.x + threadIdx.x;
    if (i < e16) {
        const int4* p = reinterpret_cast<const int4*>(dst) + i * 4;
        int4 a = p[0];
        int4 b = p[1];
        int4 c = p[2];
        int4 d = p[3];
        atomicAdd(&g_ideg[a.x], 1);
        atomicAdd(&g_ideg[a.y], 1);
        atomicAdd(&g_ideg[a.z], 1);
        atomicAdd(&g_ideg[a.w], 1);
        atomicAdd(&g_ideg[b.x], 1);
        atomicAdd(&g_ideg[b.y], 1);
        atomicAdd(&g_ideg[b.z], 1);
        atomicAdd(&g_ideg[b.w], 1);
        atomicAdd(&g_ideg[c.x], 1);
        atomicAdd(&g_ideg[c.y], 1);
        atomicAdd(&g_ideg[c.z], 1);
        atomicAdd(&g_ideg[c.w], 1);
        atomicAdd(&g_ideg[d.x], 1);
        atomicAdd(&g_ideg[d.y], 1);
        atomicAdd(&g_ideg[d.z], 1);
        atomicAdd(&g_ideg[d.w], 1);
    }
    int t = e16 * 16 + i;
    if (i < (e - e16 * 16)) {
        atomicAdd(&g_ideg[dst[t]], 1);
    }
}

// ---------------------------------------------------------------------------
// Per-node: y = x*W*rsqrt(deg+1).  (S is already zero: restored by k_final.)
__global__ void k_node(const float* __restrict__ x,
                       const float* __restrict__ W, int n4) {
    int i = blockIdx.x * blockDim.x + threadIdx.x;
    if (i < n4) {
        float w  = __ldg(W);
        int4  dg = reinterpret_cast<const int4*>(g_ideg)[i];
        float4 xv = reinterpret_cast<const float4*>(x)[i];
        float4 yv;
        yv.x = xv.x * w * rsqrtf((float)(dg.x + 1));
        yv.y = xv.y * w * rsqrtf((float)(dg.y + 1));
        yv.z = xv.z * w * rsqrtf((float)(dg.z + 1));
        yv.w = xv.w * w * rsqrtf((float)(dg.w + 1));
        reinterpret_cast<float4*>(g_y)[i] = yv;
    }
}
__global__ void k_node_tail(const float* __restrict__ x,
                            const float* __restrict__ W, int n4, int n) {
    int i = n4 * 4 + blockIdx.x * blockDim.x + threadIdx.x;
    if (i < n) {
        g_y[i] = x[i] * __ldg(W) * rsqrtf((float)(g_ideg[i] + 1));
    }
}

// ---------------------------------------------------------------------------
// Scatter: 8 edges/thread. All 8 gathers issued first (MLP=8), then 8 REDs.
__global__ void k_scatter(const int* __restrict__ src,
                          const int* __restrict__ dst, int e8, int e) {
    int i = blockIdx.x * blockDim.x + threadIdx.x;
    if (i < e8) {
        const int4* ps = reinterpret_cast<const int4*>(src) + i * 2;
        const int4* pd = reinterpret_cast<const int4*>(dst) + i * 2;
        int4 s0 = ps[0];
        int4 s1 = ps[1];
        int4 d0 = pd[0];
        int4 d1 = pd[1];
        float v0 = __ldg(&g_y[s0.x]);
        float v1 = __ldg(&g_y[s0.y]);
        float v2 = __ldg(&g_y[s0.z]);
        float v3 = __ldg(&g_y[s0.w]);
        float v4 = __ldg(&g_y[s1.x]);
        float v5 = __ldg(&g_y[s1.y]);
        float v6 = __ldg(&g_y[s1.z]);
        float v7 = __ldg(&g_y[s1.w]);
        atomicAdd(&g_S[d0.x], v0);
        atomicAdd(&g_S[d0.y], v1);
        atomicAdd(&g_S[d0.z], v2);
        atomicAdd(&g_S[d0.w], v3);
        atomicAdd(&g_S[d1.x], v4);
        atomicAdd(&g_S[d1.y], v5);
        atomicAdd(&g_S[d1.z], v6);
        atomicAdd(&g_S[d1.w], v7);
    }
    int t = e8 * 8 + i;
    if (i < (e - e8 * 8)) {
        atomicAdd(&g_S[dst[t]], __ldg(&g_y[src[t]]));
    }
}

// ---------------------------------------------------------------------------
// Finalize: out = sigmoid(rsqrt(deg+1)*(S + y) + b), then restore the
// ideg=0 / S=0 invariant for the next graph replay (streaming stores; DRAM
// is ~14% utilized so these are hidden).
__global__ void k_final(float* __restrict__ out,
                        const float* __restrict__ b, int n4) {
    int i = blockIdx.x * blockDim.x + threadIdx.x;
    if (i < n4) {
        float bb = __ldg(b);
        int4   dg = reinterpret_cast<const int4*>(g_ideg)[i];
        float4 sv = reinterpret_cast<const float4*>(g_S)[i];
        float4 yv = reinterpret_cast<const float4*>(g_y)[i];
        float4 o;
        float z0 = rsqrtf((float)(dg.x + 1)) * (sv.x + yv.x) + bb;
        float z1 = rsqrtf((float)(dg.y + 1)) * (sv.y + yv.y) + bb;
        float z2 = rsqrtf((float)(dg.z + 1)) * (sv.z + yv.z) + bb;
        float z3 = rsqrtf((float)(dg.w + 1)) * (sv.w + yv.w) + bb;
        o.x = 1.0f / (1.0f + __expf(-z0));
        o.y = 1.0f / (1.0f + __expf(-z1));
        o.z = 1.0f / (1.0f + __expf(-z2));
        o.w = 1.0f / (1.0f + __expf(-z3));
        reinterpret_cast<float4*>(out)[i] = o;
        // restore zero-state for next replay
        reinterpret_cast<int4*>(g_ideg)[i]  = make_int4(0, 0, 0, 0);
        reinterpret_cast<float4*>(g_S)[i]   = make_float4(0.f, 0.f, 0.f, 0.f);
    }
}
__global__ void k_final_tail(float* __restrict__ out,
                             const float* __restrict__ b, int n4, int n) {
    int i = n4 * 4 + blockIdx.x * blockDim.x + threadIdx.x;
    if (i < n) {
        float z = rsqrtf((float)(g_ideg[i] + 1)) * (g_S[i] + g_y[i]) + __ldg(b);
        out[i] = 1.0f / (1.0f + __expf(-z));
        g_ideg[i] = 0;
        g_S[i] = 0.0f;
    }
}

// ---------------------------------------------------------------------------
extern "C" void kernel_launch(void* const* d_in, const int* in_sizes, int n_in,
                              void* d_out, int out_size) {
    const float* x    = (const float*)d_in[0];
    const int*   eidx = (const int*)  d_in[1];
    const float* W    = (const float*)d_in[2];
    const float* b    = (const float*)d_in[3];
    float* out = (float*)d_out;

    int n = in_sizes[0];
    int e = in_sizes[1] / 2;
    const int* src = eidx;
    const int* dst = eidx + e;

    int n4  = n / 4;
    int e8  = e / 8;
    int e16 = e / 16;

    const int TPBN = 256;
    const int TPBE = 512;
    int gn4  = (n4 + TPBN - 1) / TPBN;
    int ge8  = (e8 + TPBE - 1) / TPBE;
    int ge16 = (e16 + TPBE - 1) / TPBE;

    k_degree <<<ge16, TPBE>>>(dst, e16, e);
    k_node   <<<gn4, TPBN>>>(x, W, n4);
    if (n % 4) k_node_tail<<<1, 256>>>(x, W, n4, n);
    k_scatter<<<ge8, TPBE>>>(src, dst, e8, e);
    k_final  <<<gn4, TPBN>>>(out, b, n4);
    if (n % 4) k_final_tail<<<1, 256>>>(out, b, n4, n);
}